// round 7
// baseline (speedup 1.0000x reference)
#include <cuda_runtime.h>
#include <cuda_fp16.h>
#include <stdint.h>

// DCT-III along channels via mma.sync m16n8k16 fp16 (A single, B hi/lo split).
// out[b,c,p] = sum_k M[c,k] x[b,k,p],  M[c,k] = (k==0)?1:2*cos(pi*k*(2c+1)/512)
// Parity: E[c]=sum_{even k}, O[c]=sum_{odd k}; out[c]=E+O, out[255-c]=E-O.
// Round 7: channel-split CTAs (64 c each, 128 px tile) -> 64 acc regs, <=128
// regs/thread, 64KB smem/CTA => 2 CTAs/SM with independent barriers.

#define C_DIM  256
#define HW     16384
#define NTILES 1024
#define GRID_P 148          // tile-series stride (two CTAs share a series slot)
#define THREADS 256

#define SMB 32768           // A 32KB, then B double buffer 2x16KB
#define SMEM_TOTAL 65536

// A image: [ch2][kt8][t8 8][lane 32][16B] ; t8 = eo*4 + cg*2 + mt
__device__ __align__(16) unsigned char g_A[65536];

__global__ void precompute_kernel() {
    int t = blockIdx.x * blockDim.x + threadIdx.x;   // 4096
    int ch = t >> 11;
    int kt = (t >> 8) & 7;
    int t8 = (t >> 5) & 7;
    int lane = t & 31;
    int gid = lane >> 2, tig = lane & 3;
    int eo = t8 >> 2, cg = (t8 >> 1) & 1, mt = t8 & 1;
    uint32_t w4[4];
#pragma unroll
    for (int w = 0; w < 4; ++w) {
        int c = ch * 64 + cg * 32 + mt * 16 + gid + (w & 1) * 8;
        int kap0 = tig * 2 + (w >> 1) * 8;
        float v2[2];
#pragma unroll
        for (int h = 0; h < 2; ++h) {
            int k = kt * 32 + 2 * (kap0 + h) + eo;
            if (k == 0) v2[h] = 1.0f;
            else {
                int mm = (k * (2 * c + 1)) & 1023;
                v2[h] = 2.0f * cospif((float)mm * (1.0f / 512.0f));
            }
        }
        __half2 h2 = __floats2half2_rn(v2[0], v2[1]);
        w4[w] = *(uint32_t*)&h2;
    }
    *(uint4*)(g_A + ((ch * 8 + kt) * 8 + t8) * 512 + lane * 16) =
        make_uint4(w4[0], w4[1], w4[2], w4[3]);
}

__device__ __forceinline__ void mma16816(float* c,
    uint32_t a0, uint32_t a1, uint32_t a2, uint32_t a3,
    uint32_t b0, uint32_t b1) {
    asm volatile(
        "mma.sync.aligned.m16n8k16.row.col.f32.f16.f16.f32 "
        "{%0,%1,%2,%3}, {%4,%5,%6,%7}, {%8,%9}, {%0,%1,%2,%3};"
        : "+f"(c[0]), "+f"(c[1]), "+f"(c[2]), "+f"(c[3])
        : "r"(a0), "r"(a1), "r"(a2), "r"(a3), "r"(b0), "r"(b1));
}

__global__ __launch_bounds__(THREADS, 2)
void idct_mma_kernel(const float* __restrict__ x, float* __restrict__ out) {
    extern __shared__ char sm[];
    const int tid  = threadIdx.x;
    const int lane = tid & 31;
    const int q    = lane & 3;
    const int frow = lane >> 2;
    const int wid  = tid >> 5;
    const int cg   = wid & 1;    // 32-channel group within this CTA's 64
    const int pg   = wid >> 1;   // 32-px group (0..3)

    // B producer role
    const int px  = tid & 127;
    const int par = tid >> 7;
    const int g8  = px >> 3;
    const int r   = px & 7;
    const uint32_t psw = (uint32_t)((r & 4) << 2);
    const uint32_t po1 = (uint32_t)(par * 8192 + g8 * 512) + (((uint32_t)(r * 32)) ^ psw);
    const uint32_t po2 = (uint32_t)(par * 8192 + g8 * 512) + (((uint32_t)(r * 32 + 16)) ^ psw);
    // B consumer offset
    const uint32_t bco = (((uint32_t)(frow * 32 + q * 8)) ^ ((uint32_t)((frow & 4) << 2)));

    const int chalf = blockIdx.x & 1;   // which 64-channel half this CTA owns
    int ti = blockIdx.x >> 1;           // tile index, stride GRID_P

    const float* xpb = x + (size_t)(ti >> 7) * C_DIM * HW + (ti & 127) * 128
                         + (size_t)par * HW + px;
    float v[16];
#pragma unroll
    for (int i = 0; i < 16; ++i) v[i] = xpb[(size_t)(2 * i) * HW];

    // stage this CTA's A half once (32KB)
    {
        const uint4* src = (const uint4*)g_A + chalf * 2048;
        uint4* dst = (uint4*)sm;
#pragma unroll
        for (int i = 0; i < 8; ++i) dst[tid + 256 * i] = src[tid + 256 * i];
    }

    float acc[2][2][4][4];
#pragma unroll
    for (int a = 0; a < 2; a++)
#pragma unroll
        for (int e = 0; e < 2; e++)
#pragma unroll
            for (int b = 0; b < 4; b++)
#pragma unroll
                for (int j = 0; j < 4; j++) acc[a][e][b][j] = 0.0f;

    while (ti < NTILES) {
        const float* xnb = xpb;

#pragma unroll 1
        for (int kt = 0; kt < 8; ++kt) {
            const uint32_t buf = (uint32_t)(kt & 1) * 16384;

            // convert v -> fp16 hi + lo, fragment word order
            uint32_t hw_[8], lw_[8];
            const int Wa[8] = {0, 8, 2, 10, 4, 12, 6, 14};
#pragma unroll
            for (int w = 0; w < 8; ++w) {
                int a = Wa[w];
                __half2 h2 = __floats2half2_rn(v[a], v[a + 1]);
                float2 hf = __half22float2(h2);
                __half2 l2 = __floats2half2_rn(v[a] - hf.x, v[a + 1] - hf.y);
                hw_[w] = *(uint32_t*)&h2;
                lw_[w] = *(uint32_t*)&l2;
            }
            {
                char* bb = sm + SMB + buf;
                *(uint4*)(bb + po1) = make_uint4(hw_[0], hw_[1], hw_[2], hw_[3]);
                *(uint4*)(bb + po2) = make_uint4(hw_[4], hw_[5], hw_[6], hw_[7]);
                *(uint4*)(bb + 256 + po1) = make_uint4(lw_[0], lw_[1], lw_[2], lw_[3]);
                *(uint4*)(bb + 256 + po2) = make_uint4(lw_[4], lw_[5], lw_[6], lw_[7]);
            }

            // prefetch next k chunk (or next tile's kt0)
            const float* nb;
            if (kt < 7) {
                nb = xpb + (size_t)(32 * (kt + 1)) * HW;
            } else {
                int tn = (ti + GRID_P < NTILES) ? (ti + GRID_P) : ti;
                nb = x + (size_t)(tn >> 7) * C_DIM * HW + (tn & 127) * 128
                       + (size_t)par * HW + px;
                xnb = nb;
            }
#pragma unroll
            for (int i = 0; i < 16; ++i) v[i] = nb[(size_t)(2 * i) * HW];

            __syncthreads();

            // per-parity: load B frags (16 regs live), then A frags + mma
#pragma unroll
            for (int eo = 0; eo < 2; ++eo) {
                uint2 Bh[4], Bl[4];
#pragma unroll
                for (int nt = 0; nt < 4; ++nt) {
                    const char* bb = sm + SMB + buf + eo * 8192 +
                                     (pg * 4 + nt) * 512 + bco;
                    Bh[nt] = *(const uint2*)(bb);
                    Bl[nt] = *(const uint2*)(bb + 256);
                }
#pragma unroll
                for (int mt = 0; mt < 2; ++mt) {
                    uint4 Aw = *(const uint4*)(sm +
                        ((kt * 8) + eo * 4 + cg * 2 + mt) * 512 + lane * 16);
#pragma unroll
                    for (int nt = 0; nt < 4; ++nt) {
                        mma16816(acc[mt][eo][nt], Aw.x, Aw.y, Aw.z, Aw.w,
                                 Bh[nt].x, Bh[nt].y);
                        mma16816(acc[mt][eo][nt], Aw.x, Aw.y, Aw.z, Aw.w,
                                 Bl[nt].x, Bl[nt].y);
                    }
                }
            }
        }

        // ---- epilogue: parity combine in regs, direct sector-aligned STG ----
        {
            float* ob = out + (size_t)(ti >> 7) * C_DIM * HW + (ti & 127) * 128;
#pragma unroll
            for (int mt = 0; mt < 2; ++mt) {
                int c = chalf * 64 + cg * 32 + mt * 16 + frow;
#pragma unroll
                for (int nt = 0; nt < 4; ++nt) {
                    int pxo = pg * 32 + nt * 8 + q * 2;
                    float* E = acc[mt][0][nt];
                    float* O = acc[mt][1][nt];
                    *(float2*)&ob[(size_t)c * HW + pxo] =
                        make_float2(E[0] + O[0], E[1] + O[1]);
                    *(float2*)&ob[(size_t)(255 - c) * HW + pxo] =
                        make_float2(E[0] - O[0], E[1] - O[1]);
                    *(float2*)&ob[(size_t)(c + 8) * HW + pxo] =
                        make_float2(E[2] + O[2], E[3] + O[3]);
                    *(float2*)&ob[(size_t)(247 - c) * HW + pxo] =
                        make_float2(E[2] - O[2], E[3] - O[3]);
                    E[0] = E[1] = E[2] = E[3] = 0.0f;
                    O[0] = O[1] = O[2] = O[3] = 0.0f;
                }
            }
        }

        ti += GRID_P;
        xpb = xnb;
    }
}

extern "C" void kernel_launch(void* const* d_in, const int* in_sizes, int n_in,
                              void* d_out, int out_size) {
    const float* x = (const float*)d_in[0];
    float* out = (float*)d_out;

    cudaFuncSetAttribute(idct_mma_kernel,
                         cudaFuncAttributeMaxDynamicSharedMemorySize, SMEM_TOTAL);
    precompute_kernel<<<16, 256>>>();
    idct_mma_kernel<<<2 * GRID_P, THREADS, SMEM_TOTAL>>>(x, out);
}

// round 9
// speedup vs baseline: 1.1766x; 1.1766x over previous
#include <cuda_runtime.h>
#include <cuda_fp16.h>
#include <stdint.h>

// DCT-III along channels via mma.sync m16n8k16 fp16 (A single, B hi/lo split).
// out[b,c,p] = sum_k M[c,k] x[b,k,p],  M[c,k] = (k==0)?1:2*cos(pi*k*(2c+1)/512)
// Parity: E[c]=sum_{even k}, O[c]=sum_{odd k}; out[c]=E+O, out[255-c]=E-O.
// Round 9: R8 pixel-split design with FIXED producer k-strides:
//   thread(half h) loads global k offsets par + h*8 + {0,2,4,6} and +16,
//   i.e. k-local h*4+j and 8+h*4+j  (fragment needs k stride 2, not 4).

#define C_DIM  256
#define HW     16384
#define NTILES 1024
#define GRID_P 148
#define THREADS 256

#define SMB 65536            // A 64KB, then B double buffer 2x8KB
#define SMEM_TOTAL 81920

// A image: [kt8][t16][lane 32][16B] ; t16 = eo*8 + (c>>4)
__device__ __align__(16) unsigned char g_A[65536];

__global__ void precompute_kernel() {
    int t = blockIdx.x * blockDim.x + threadIdx.x;   // 4096 = [kt][t16][lane]
    int kt = t >> 9;
    int t16 = (t >> 5) & 15;
    int lane = t & 31;
    int gid = lane >> 2, tig = lane & 3;
    int eo = t16 >> 3;
    uint32_t w4[4];
#pragma unroll
    for (int w = 0; w < 4; ++w) {
        int m = t16 * 16 + gid + (w & 1) * 8;
        int c = m & 127;
        int kap0 = tig * 2 + (w >> 1) * 8;
        float v2[2];
#pragma unroll
        for (int h = 0; h < 2; ++h) {
            int k = kt * 32 + 2 * (kap0 + h) + eo;
            if (k == 0) v2[h] = 1.0f;
            else {
                int mm = (k * (2 * c + 1)) & 1023;
                v2[h] = 2.0f * cospif((float)mm * (1.0f / 512.0f));
            }
        }
        __half2 h2 = __floats2half2_rn(v2[0], v2[1]);
        w4[w] = *(uint32_t*)&h2;
    }
    *(uint4*)(g_A + (kt * 16 + t16) * 512 + lane * 16) =
        make_uint4(w4[0], w4[1], w4[2], w4[3]);
}

__device__ __forceinline__ void mma16816(float* c,
    uint32_t a0, uint32_t a1, uint32_t a2, uint32_t a3,
    uint32_t b0, uint32_t b1) {
    asm volatile(
        "mma.sync.aligned.m16n8k16.row.col.f32.f16.f16.f32 "
        "{%0,%1,%2,%3}, {%4,%5,%6,%7}, {%8,%9}, {%0,%1,%2,%3};"
        : "+f"(c[0]), "+f"(c[1]), "+f"(c[2]), "+f"(c[3])
        : "r"(a0), "r"(a1), "r"(a2), "r"(a3), "r"(b0), "r"(b1));
}

__global__ __launch_bounds__(THREADS, 2)
void idct_mma_kernel(const float* __restrict__ x, float* __restrict__ out) {
    extern __shared__ char sm[];
    const int tid  = threadIdx.x;
    const int lane = tid & 31;
    const int q    = lane & 3;
    const int frow = lane >> 2;
    const int wid  = tid >> 5;
    const int cg   = wid & 3;    // 32-channel group (0..3)
    const int pg   = wid >> 2;   // 32-px group (0..1)

    // B producer role: one 16B word-quad per thread (hi) + one (lo)
    const int px   = tid & 63;
    const int par  = (tid >> 6) & 1;
    const int half = tid >> 7;          // word quad 0..3 / 4..7
    const int g8   = px >> 3;
    const int r    = px & 7;
    const uint32_t psw = (uint32_t)((r & 4) << 2);
    const uint32_t po  = (uint32_t)(par * 4096 + g8 * 512 + r * 32) +
                         (((uint32_t)(half * 16)) ^ psw);
    // B consumer offset
    const uint32_t bco = (((uint32_t)(frow * 32)) +
                          (((uint32_t)(q * 8)) ^ ((uint32_t)((frow & 4) << 2))));

    const int chalf = blockIdx.x & 1;   // which 64-px half of the tile
    int ti = blockIdx.x >> 1;

    // producer gmem base: global k offset = par + half*8 (+2j, +16+2j below)
    const float* xpb = x + (size_t)(ti >> 7) * C_DIM * HW + (ti & 127) * 128
                         + chalf * 64 + px + (size_t)(par + half * 8) * HW;
    float v[8];
#pragma unroll
    for (int j = 0; j < 4; ++j) {
        v[j]     = xpb[(size_t)(2 * j) * HW];
        v[4 + j] = xpb[(size_t)(16 + 2 * j) * HW];
    }

    // stage A once (64KB)
    {
        const uint4* src = (const uint4*)g_A;
        uint4* dst = (uint4*)sm;
#pragma unroll
        for (int i = 0; i < 16; ++i) dst[tid + 256 * i] = src[tid + 256 * i];
    }

    float acc[2][2][4][4];
#pragma unroll
    for (int a = 0; a < 2; a++)
#pragma unroll
        for (int e = 0; e < 2; e++)
#pragma unroll
            for (int b = 0; b < 4; b++)
#pragma unroll
                for (int j = 0; j < 4; j++) acc[a][e][b][j] = 0.0f;

    while (ti < NTILES) {
        const float* xnb = xpb;

#pragma unroll 1
        for (int kt = 0; kt < 8; ++kt) {
            const uint32_t buf = (uint32_t)(kt & 1) * 8192;

            // convert v -> fp16 hi + lo word quads
            // quad words: (v0,v1),(v4,v5),(v2,v3),(v6,v7)
            uint32_t hw_[4], lw_[4];
            const int Wp[4] = {0, 4, 2, 6};
#pragma unroll
            for (int w = 0; w < 4; ++w) {
                int a = Wp[w];
                __half2 h2 = __floats2half2_rn(v[a], v[a + 1]);
                float2 hf = __half22float2(h2);
                __half2 l2 = __floats2half2_rn(v[a] - hf.x, v[a + 1] - hf.y);
                hw_[w] = *(uint32_t*)&h2;
                lw_[w] = *(uint32_t*)&l2;
            }
            {
                char* bb = sm + SMB + buf + po;
                *(uint4*)(bb)       = make_uint4(hw_[0], hw_[1], hw_[2], hw_[3]);
                *(uint4*)(bb + 256) = make_uint4(lw_[0], lw_[1], lw_[2], lw_[3]);
            }

            // prefetch next k chunk (or next tile's kt0)
            const float* nb;
            if (kt < 7) {
                nb = xpb + (size_t)(32 * (kt + 1)) * HW;
            } else {
                int tn = (ti + GRID_P < NTILES) ? (ti + GRID_P) : ti;
                nb = x + (size_t)(tn >> 7) * C_DIM * HW + (tn & 127) * 128
                       + chalf * 64 + px + (size_t)(par + half * 8) * HW;
                xnb = nb;
            }
#pragma unroll
            for (int j = 0; j < 4; ++j) {
                v[j]     = nb[(size_t)(2 * j) * HW];
                v[4 + j] = nb[(size_t)(16 + 2 * j) * HW];
            }

            __syncthreads();

            // per-parity: B frags then A frags + mma
#pragma unroll
            for (int eo = 0; eo < 2; ++eo) {
                uint2 Bh[4], Bl[4];
#pragma unroll
                for (int nt = 0; nt < 4; ++nt) {
                    const char* bb = sm + SMB + buf + eo * 4096 +
                                     (pg * 4 + nt) * 512 + bco;
                    Bh[nt] = *(const uint2*)(bb);
                    Bl[nt] = *(const uint2*)(bb + 256);
                }
#pragma unroll
                for (int mt = 0; mt < 2; ++mt) {
                    uint4 Aw = *(const uint4*)(sm +
                        (kt * 16 + eo * 8 + cg * 2 + mt) * 512 + lane * 16);
#pragma unroll
                    for (int nt = 0; nt < 4; ++nt) {
                        mma16816(acc[mt][eo][nt], Aw.x, Aw.y, Aw.z, Aw.w,
                                 Bh[nt].x, Bh[nt].y);
                        mma16816(acc[mt][eo][nt], Aw.x, Aw.y, Aw.z, Aw.w,
                                 Bl[nt].x, Bl[nt].y);
                    }
                }
            }
        }

        // ---- epilogue: parity combine in regs, direct sector-aligned STG ----
        {
            float* ob = out + (size_t)(ti >> 7) * C_DIM * HW + (ti & 127) * 128
                            + chalf * 64;
#pragma unroll
            for (int mt = 0; mt < 2; ++mt) {
                int c = cg * 32 + mt * 16 + frow;
#pragma unroll
                for (int nt = 0; nt < 4; ++nt) {
                    int pxo = pg * 32 + nt * 8 + q * 2;
                    float* E = acc[mt][0][nt];
                    float* O = acc[mt][1][nt];
                    *(float2*)&ob[(size_t)c * HW + pxo] =
                        make_float2(E[0] + O[0], E[1] + O[1]);
                    *(float2*)&ob[(size_t)(255 - c) * HW + pxo] =
                        make_float2(E[0] - O[0], E[1] - O[1]);
                    *(float2*)&ob[(size_t)(c + 8) * HW + pxo] =
                        make_float2(E[2] + O[2], E[3] + O[3]);
                    *(float2*)&ob[(size_t)(247 - c) * HW + pxo] =
                        make_float2(E[2] - O[2], E[3] - O[3]);
                    E[0] = E[1] = E[2] = E[3] = 0.0f;
                    O[0] = O[1] = O[2] = O[3] = 0.0f;
                }
            }
        }

        ti += GRID_P;
        xpb = xnb;
    }
}

extern "C" void kernel_launch(void* const* d_in, const int* in_sizes, int n_in,
                              void* d_out, int out_size) {
    const float* x = (const float*)d_in[0];
    float* out = (float*)d_out;

    cudaFuncSetAttribute(idct_mma_kernel,
                         cudaFuncAttributeMaxDynamicSharedMemorySize, SMEM_TOTAL);
    precompute_kernel<<<16, 256>>>();
    idct_mma_kernel<<<2 * GRID_P, THREADS, SMEM_TOTAL>>>(x, out);
}

// round 10
// speedup vs baseline: 1.1936x; 1.0144x over previous
#include <cuda_runtime.h>
#include <cuda_fp16.h>
#include <stdint.h>

// DCT-III along channels via mma.sync m16n8k16 fp16 (A single, B hi/lo split).
// out[b,c,p] = sum_k M[c,k] x[b,k,p],  M[c,k] = (k==0)?1:2*cos(pi*k*(2c+1)/512)
// Parity: E[c]=sum_{even k}, O[c]=sum_{odd k}; out[c]=E+O, out[255-c]=E-O.
// Round 10: warp specialization. 8 consumer warps (R6 fragment path) + 4
// producer warps (LDG/cvt/STS) over a 4-stage mbarrier ring. No lockstep
// __syncthreads in the main loop.

#define C_DIM  256
#define HW     16384
#define NTILES 1024
#define GRID_P 148
#define THREADS 384
#define NSTAGE 4

#define SMB      65536                       // A 64KB below, B ring above
#define MBAR_OFF (SMB + NSTAGE * 16384)      // 131072
#define SMEM_TOTAL (MBAR_OFF + 128)

// A image: [kt8][t16][lane 32][16B] ; t16 = eo*8 + (c>>4)
__device__ __align__(16) unsigned char g_A[65536];

__global__ void precompute_kernel() {
    int t = blockIdx.x * blockDim.x + threadIdx.x;   // 4096 = [kt][t16][lane]
    int kt = t >> 9;
    int t16 = (t >> 5) & 15;
    int lane = t & 31;
    int gid = lane >> 2, tig = lane & 3;
    int eo = t16 >> 3;
    uint32_t w4[4];
#pragma unroll
    for (int w = 0; w < 4; ++w) {
        int m = t16 * 16 + gid + (w & 1) * 8;
        int c = m & 127;
        int kap0 = tig * 2 + (w >> 1) * 8;
        float v2[2];
#pragma unroll
        for (int h = 0; h < 2; ++h) {
            int k = kt * 32 + 2 * (kap0 + h) + eo;
            if (k == 0) v2[h] = 1.0f;
            else {
                int mm = (k * (2 * c + 1)) & 1023;
                v2[h] = 2.0f * cospif((float)mm * (1.0f / 512.0f));
            }
        }
        __half2 h2 = __floats2half2_rn(v2[0], v2[1]);
        w4[w] = *(uint32_t*)&h2;
    }
    *(uint4*)(g_A + (kt * 16 + t16) * 512 + lane * 16) =
        make_uint4(w4[0], w4[1], w4[2], w4[3]);
}

__device__ __forceinline__ uint32_t smem_u32(const void* p) {
    uint32_t a;
    asm("{ .reg .u64 t; cvta.to.shared.u64 t, %1; cvt.u32.u64 %0, t; }"
        : "=r"(a) : "l"(p));
    return a;
}
#define MBARRIER_INIT(a, c) \
    asm volatile("mbarrier.init.shared.b64 [%0], %1;" :: "r"(a), "r"(c) : "memory")
#define MBARRIER_ARRIVE(a) \
    asm volatile("mbarrier.arrive.shared.b64 _, [%0];" :: "r"(a) : "memory")
#define MBARRIER_WAIT(a, par) \
    asm volatile("{\n\t.reg .pred P;\n\tWL%=:\n\t" \
        "mbarrier.try_wait.parity.acquire.cta.shared::cta.b64 P, [%0], %1, 0x989680;\n\t" \
        "@P bra.uni WD%=;\n\tbra.uni WL%=;\n\tWD%=:\n\t}" :: "r"(a), "r"(par) : "memory")

__device__ __forceinline__ void mma16816(float* c,
    uint32_t a0, uint32_t a1, uint32_t a2, uint32_t a3,
    uint32_t b0, uint32_t b1) {
    asm volatile(
        "mma.sync.aligned.m16n8k16.row.col.f32.f16.f16.f32 "
        "{%0,%1,%2,%3}, {%4,%5,%6,%7}, {%8,%9}, {%0,%1,%2,%3};"
        : "+f"(c[0]), "+f"(c[1]), "+f"(c[2]), "+f"(c[3])
        : "r"(a0), "r"(a1), "r"(a2), "r"(a3), "r"(b0), "r"(b1));
}

__global__ __launch_bounds__(THREADS, 1)
void idct_mma_kernel(const float* __restrict__ x, float* __restrict__ out) {
    extern __shared__ char sm[];
    const uint32_t mb = smem_u32(sm) + MBAR_OFF;   // full[s]@+s*16, empty[s]@+s*16+8
    const int tid  = threadIdx.x;
    const int lane = tid & 31;
    const int wid  = tid >> 5;
    const int bid  = blockIdx.x;

    const int nt_cta = (NTILES - bid + GRID_P - 1) / GRID_P;
    const int total  = nt_cta * 8;

    if (tid == 0) {
#pragma unroll
        for (int s = 0; s < NSTAGE; ++s) {
            MBARRIER_INIT(mb + s * 16, 128);       // full: producer threads
            MBARRIER_INIT(mb + s * 16 + 8, 256);   // empty: consumer threads
        }
    }
    // stage A once (64KB) — consumer threads
    if (tid < 256) {
        const uint4* src = (const uint4*)g_A;
        uint4* dst = (uint4*)sm;
#pragma unroll
        for (int i = 0; i < 16; ++i) dst[tid + 256 * i] = src[tid + 256 * i];
    }
    __syncthreads();

    if (wid >= 8) {
        // ================= PRODUCER (4 warps, 128 threads) =================
        const int px  = tid - 256;          // 0..127
        const int g8  = px >> 3;
        const int r   = px & 7;
        const uint32_t psw = (uint32_t)((r & 4) << 2);
        const uint32_t o1  = ((uint32_t)(r * 32)) ^ psw;
        const uint32_t o2  = ((uint32_t)(r * 32 + 16)) ^ psw;
        const int Wa[8] = {0, 8, 2, 10, 4, 12, 6, 14};

        int ti = bid, kt = 0;
        const float* xp = x + (size_t)(ti >> 7) * C_DIM * HW + (ti & 127) * 128 + px;
        float v[32];
#pragma unroll
        for (int l = 0; l < 32; ++l) v[l] = xp[(size_t)l * HW];

        int s = 0, ph = 1;
        for (int n = 0; n < total; ++n) {
            MBARRIER_WAIT(mb + s * 16 + 8, ph);    // wait empty
            char* st = sm + SMB + s * 16384 + g8 * 512;
#pragma unroll
            for (int p = 0; p < 2; ++p) {
                uint32_t hw_[8], lw_[8];
#pragma unroll
                for (int w = 0; w < 8; ++w) {
                    int i0 = 2 * Wa[w] + p;
                    __half2 h2 = __floats2half2_rn(v[i0], v[i0 + 2]);
                    float2 hf = __half22float2(h2);
                    __half2 l2 = __floats2half2_rn(v[i0] - hf.x, v[i0 + 2] - hf.y);
                    hw_[w] = *(uint32_t*)&h2;
                    lw_[w] = *(uint32_t*)&l2;
                }
                char* bb = st + p * 8192;
                *(uint4*)(bb + o1)       = make_uint4(hw_[0], hw_[1], hw_[2], hw_[3]);
                *(uint4*)(bb + o2)       = make_uint4(hw_[4], hw_[5], hw_[6], hw_[7]);
                *(uint4*)(bb + 256 + o1) = make_uint4(lw_[0], lw_[1], lw_[2], lw_[3]);
                *(uint4*)(bb + 256 + o2) = make_uint4(lw_[4], lw_[5], lw_[6], lw_[7]);
            }
            MBARRIER_ARRIVE(mb + s * 16);          // full
            s = (s + 1) & (NSTAGE - 1);
            if (s == 0) ph ^= 1;

            if (++kt == 8) { kt = 0; ti += GRID_P; }
            if (n + 1 < total) {
                xp = x + (size_t)(ti >> 7) * C_DIM * HW + (ti & 127) * 128
                       + (size_t)(kt * 32) * HW + px;
#pragma unroll
                for (int l = 0; l < 32; ++l) v[l] = xp[(size_t)l * HW];
            }
        }
    } else {
        // ================= CONSUMER (8 warps, 256 threads) =================
        const int q    = lane & 3;
        const int frow = lane >> 2;
        const int cg   = wid & 1;    // 64-channel group
        const int pg   = wid >> 1;   // 32-px group (0..3)
        const uint32_t bco = (((uint32_t)(frow * 32)) +
                              (((uint32_t)(q * 8)) ^ ((uint32_t)((frow & 4) << 2))));

        float acc[4][2][4][4];
#pragma unroll
        for (int a = 0; a < 4; a++)
#pragma unroll
            for (int e = 0; e < 2; e++)
#pragma unroll
                for (int b = 0; b < 4; b++)
#pragma unroll
                    for (int j = 0; j < 4; j++) acc[a][e][b][j] = 0.0f;

        int ti = bid;
        int s = 0, ph = 0;
        while (ti < NTILES) {
#pragma unroll 1
            for (int kt = 0; kt < 8; ++kt) {
                MBARRIER_WAIT(mb + s * 16, ph);    // wait full

                uint2 Bh[2][4], Bl[2][4];
#pragma unroll
                for (int pr = 0; pr < 2; ++pr)
#pragma unroll
                    for (int nt = 0; nt < 4; ++nt) {
                        const char* bb = sm + SMB + s * 16384 + pr * 8192 +
                                         (pg * 4 + nt) * 512 + bco;
                        Bh[pr][nt] = *(const uint2*)(bb);
                        Bl[pr][nt] = *(const uint2*)(bb + 256);
                    }
                MBARRIER_ARRIVE(mb + s * 16 + 8);  // empty (frags in regs)
                s = (s + 1) & (NSTAGE - 1);
                if (s == 0) ph ^= 1;

#pragma unroll
                for (int eo = 0; eo < 2; ++eo)
#pragma unroll
                    for (int mt = 0; mt < 4; ++mt) {
                        uint4 Aw = *(const uint4*)(sm +
                            (kt * 16 + eo * 8 + cg * 4 + mt) * 512 + lane * 16);
#pragma unroll
                        for (int nt = 0; nt < 4; ++nt) {
                            mma16816(acc[mt][eo][nt], Aw.x, Aw.y, Aw.z, Aw.w,
                                     Bh[eo][nt].x, Bh[eo][nt].y);
                            mma16816(acc[mt][eo][nt], Aw.x, Aw.y, Aw.z, Aw.w,
                                     Bl[eo][nt].x, Bl[eo][nt].y);
                        }
                    }
            }

            // ---- epilogue: parity combine in regs, sector-aligned STG ----
            {
                float* ob = out + (size_t)(ti >> 7) * C_DIM * HW + (ti & 127) * 128;
#pragma unroll
                for (int mt = 0; mt < 4; ++mt) {
                    int c = cg * 64 + mt * 16 + frow;
#pragma unroll
                    for (int nt = 0; nt < 4; ++nt) {
                        int pxo = pg * 32 + nt * 8 + q * 2;
                        float* E = acc[mt][0][nt];
                        float* O = acc[mt][1][nt];
                        *(float2*)&ob[(size_t)c * HW + pxo] =
                            make_float2(E[0] + O[0], E[1] + O[1]);
                        *(float2*)&ob[(size_t)(255 - c) * HW + pxo] =
                            make_float2(E[0] - O[0], E[1] - O[1]);
                        *(float2*)&ob[(size_t)(c + 8) * HW + pxo] =
                            make_float2(E[2] + O[2], E[3] + O[3]);
                        *(float2*)&ob[(size_t)(247 - c) * HW + pxo] =
                            make_float2(E[2] - O[2], E[3] - O[3]);
                        E[0] = E[1] = E[2] = E[3] = 0.0f;
                        O[0] = O[1] = O[2] = O[3] = 0.0f;
                    }
                }
            }
            ti += GRID_P;
        }
    }
}

extern "C" void kernel_launch(void* const* d_in, const int* in_sizes, int n_in,
                              void* d_out, int out_size) {
    const float* x = (const float*)d_in[0];
    float* out = (float*)d_out;

    cudaFuncSetAttribute(idct_mma_kernel,
                         cudaFuncAttributeMaxDynamicSharedMemorySize, SMEM_TOTAL);
    precompute_kernel<<<16, 256>>>();
    idct_mma_kernel<<<GRID_P, THREADS, SMEM_TOTAL>>>(x, out);
}